// round 7
// baseline (speedup 1.0000x reference)
#include <cuda_runtime.h>
#include <math.h>

// Problem constants: B=1048576, M=8, K=3, R=8
#define M 8
#define Kc 3
#define R 8
#define NPAIR 4          // rule pairs (f32x2 lanes = 2 rules)
#define PW 56            // floats per packed pair row (26 entries*2, padded; 16B aligned)
#define TPB 128          // threads per block
#define ROWS_PER_BLOCK (TPB * 2)

typedef unsigned long long u64;

static __device__ __forceinline__ u64 pk2(float lo, float hi) {
    u64 r; asm("mov.b64 %0, {%1,%2};" : "=l"(r) : "f"(lo), "f"(hi)); return r;
}
static __device__ __forceinline__ void upk2(u64 v, float& lo, float& hi) {
    asm("mov.b64 {%0,%1}, %2;" : "=f"(lo), "=f"(hi) : "l"(v));
}
static __device__ __forceinline__ u64 fma2(u64 a, u64 b, u64 c) {
    u64 d; asm("fma.rn.f32x2 %0, %1, %2, %3;" : "=l"(d) : "l"(a), "l"(b), "l"(c)); return d;
}
static __device__ __forceinline__ float ex2f(float v) {
    float r; asm("ex2.approx.f32 %0, %1;" : "=f"(r) : "f"(v)); return r;
}
static __device__ __forceinline__ float rcpf(float v) {
    float r; asm("rcp.approx.f32 %0, %1;" : "=f"(r) : "f"(v)); return r;
}

__global__ __launch_bounds__(TPB, 8)
void anfis_kernel(const float* __restrict__ x,
                  const float* __restrict__ c,
                  const float* __restrict__ log_sigma,
                  const float* __restrict__ cons,      // (R, M+1)
                  const int*   __restrict__ rules,     // (R, M)
                  float* __restrict__ out, int B)
{
    // Packed entry j (float2 over rule pair p = rules 2p,2p+1):
    //  j=0..7 : a_m = -h*log2(e)
    //  j=8..15: b_m = 2*h*c*log2(e)
    //  j=16   : k0  = -(sum h*c^2)*log2(e)
    //  j=17   : bias ; j=18..25: w_m
    __shared__ float s_raw[R][26];
    __shared__ __align__(16) float s_pack[NPAIR * PW];

    const int tid = threadIdx.x;
    const float L2E = 1.4426950408889634f;

    if (tid < R) {
        const int r = tid;
        float k0 = 0.f;
        #pragma unroll
        for (int m = 0; m < M; m++) {
            int k = rules[r * M + m];
            float sg = expf(log_sigma[m * Kc + k]) + 1e-6f;
            float h  = 0.5f / (sg * sg);
            float cc = c[m * Kc + k];
            s_raw[r][m]      = -h * L2E;
            s_raw[r][8 + m]  = 2.f * h * cc * L2E;
            k0 -= h * cc * cc;
            s_raw[r][18 + m] = cons[r * (M + 1) + 1 + m];
        }
        s_raw[r][16] = k0 * L2E;
        s_raw[r][17] = cons[r * (M + 1)];
    }
    __syncthreads();
    if (tid < NPAIR * 28) {
        const int p = tid / 28, j = tid % 28;
        float v0 = (j < 26) ? s_raw[2 * p][j]     : 0.f;
        float v1 = (j < 26) ? s_raw[2 * p + 1][j] : 0.f;
        s_pack[p * PW + 2 * j]     = v0;
        s_pack[p * PW + 2 * j + 1] = v1;
    }
    __syncthreads();

    // two rows per thread, stride blockDim for coalescing
    const int b0 = blockIdx.x * ROWS_PER_BLOCK + tid;
    const int b1 = b0 + TPB;
    if (b0 >= B) return;

    // ---- load both x rows (32B each, coalesced) ----
    const float4 xa0 = *(const float4*)(x + (size_t)b0 * M);
    const float4 xb0 = *(const float4*)(x + (size_t)b0 * M + 4);
    const float4 xa1 = *(const float4*)(x + (size_t)b1 * M);
    const float4 xb1 = *(const float4*)(x + (size_t)b1 * M + 4);

    u64 p0[M], p1[M];
    p0[0]=pk2(xa0.x,xa0.x); p0[1]=pk2(xa0.y,xa0.y); p0[2]=pk2(xa0.z,xa0.z); p0[3]=pk2(xa0.w,xa0.w);
    p0[4]=pk2(xb0.x,xb0.x); p0[5]=pk2(xb0.y,xb0.y); p0[6]=pk2(xb0.z,xb0.z); p0[7]=pk2(xb0.w,xb0.w);
    p1[0]=pk2(xa1.x,xa1.x); p1[1]=pk2(xa1.y,xa1.y); p1[2]=pk2(xa1.z,xa1.z); p1[3]=pk2(xa1.w,xa1.w);
    p1[4]=pk2(xb1.x,xb1.x); p1[5]=pk2(xb1.y,xb1.y); p1[6]=pk2(xb1.z,xb1.z); p1[7]=pk2(xb1.w,xb1.w);

    float f0[R], f1[R], yr0[R], yr1[R];
    float fs0 = 0.f, fs1 = 0.f;

    #pragma unroll
    for (int p = 0; p < NPAIR; p++) {
        const u64* S = (const u64*)(s_pack + p * PW);  // 26 packed entries

        u64 e0 = S[16], e1 = S[16];
        u64 t0 = S[17], t1 = S[17];
        #pragma unroll
        for (int m = 0; m < M; m++) {
            const u64 A = S[m], Bc = S[8 + m], W = S[18 + m];
            e0 = fma2(fma2(A, p0[m], Bc), p0[m], e0);
            e1 = fma2(fma2(A, p1[m], Bc), p1[m], e1);
            t0 = fma2(W, p0[m], t0);
            t1 = fma2(W, p1[m], t1);
        }

        float ea, eb;
        upk2(e0, ea, eb);
        float fa = ex2f(ea), fb = ex2f(eb);
        f0[2*p] = fa; f0[2*p+1] = fb; fs0 += fa + fb;
        upk2(e1, ea, eb);
        fa = ex2f(ea); fb = ex2f(eb);
        f1[2*p] = fa; f1[2*p+1] = fb; fs1 += fa + fb;

        upk2(t0, yr0[2*p], yr0[2*p+1]);
        upk2(t1, yr1[2*p], yr1[2*p+1]);
    }

    // ---- store y_r (needs no normalization) ----
    float4* yo0 = (float4*)(out + (size_t)B * 9 + (size_t)b0 * R);
    yo0[0] = make_float4(yr0[0], yr0[1], yr0[2], yr0[3]);
    yo0[1] = make_float4(yr0[4], yr0[5], yr0[6], yr0[7]);
    float4* yo1 = (float4*)(out + (size_t)B * 9 + (size_t)b1 * R);
    yo1[0] = make_float4(yr1[0], yr1[1], yr1[2], yr1[3]);
    yo1[1] = make_float4(yr1[4], yr1[5], yr1[6], yr1[7]);

    const float inv0 = rcpf(fs0 + 1e-8f);
    const float inv1 = rcpf(fs1 + 1e-8f);

    float wn0[R], wn1[R];
    float y0 = 0.f, y1 = 0.f;
    #pragma unroll
    for (int r = 0; r < R; r++) {
        wn0[r] = f0[r] * inv0;
        wn1[r] = f1[r] * inv1;
        y0 = fmaf(wn0[r], yr0[r], y0);
        y1 = fmaf(wn1[r], yr1[r], y1);
    }

    out[b0] = y0;
    out[b1] = y1;

    float4* wo0 = (float4*)(out + (size_t)B + (size_t)b0 * R);
    wo0[0] = make_float4(wn0[0], wn0[1], wn0[2], wn0[3]);
    wo0[1] = make_float4(wn0[4], wn0[5], wn0[6], wn0[7]);
    float4* wo1 = (float4*)(out + (size_t)B + (size_t)b1 * R);
    wo1[0] = make_float4(wn1[0], wn1[1], wn1[2], wn1[3]);
    wo1[1] = make_float4(wn1[4], wn1[5], wn1[6], wn1[7]);
}

extern "C" void kernel_launch(void* const* d_in, const int* in_sizes, int n_in,
                              void* d_out, int out_size)
{
    const float* x         = (const float*)d_in[0];
    const float* c         = (const float*)d_in[1];
    const float* log_sigma = (const float*)d_in[2];
    const float* cons      = (const float*)d_in[3];
    const int*   rules     = (const int*)d_in[4];
    float* out = (float*)d_out;

    const int B = in_sizes[0] / M;   // 1048576
    const int blocks = (B + ROWS_PER_BLOCK - 1) / ROWS_PER_BLOCK;  // 4096
    anfis_kernel<<<blocks, TPB>>>(x, c, log_sigma, cons, rules, out, B);
}

// round 8
// speedup vs baseline: 1.1125x; 1.1125x over previous
#include <cuda_runtime.h>
#include <math.h>

// Problem constants: B=1048576, M=8, K=3, R=8
#define M 8
#define Kc 3
#define R 8
#define NPAIR 4          // rule pairs (f32x2 lanes = 2 rules)
#define PW 56            // floats per packed pair row (26 entries*2, padded; 16B aligned)
#define TPB 128          // threads per block
#define RPT 4            // rows per thread
#define ROWS_PER_BLOCK (TPB * RPT)

typedef unsigned long long u64;

static __device__ __forceinline__ u64 pk2(float lo, float hi) {
    u64 r; asm("mov.b64 %0, {%1,%2};" : "=l"(r) : "f"(lo), "f"(hi)); return r;
}
static __device__ __forceinline__ void upk2(u64 v, float& lo, float& hi) {
    asm("mov.b64 {%0,%1}, %2;" : "=f"(lo), "=f"(hi) : "l"(v));
}
static __device__ __forceinline__ u64 fma2(u64 a, u64 b, u64 c) {
    u64 d; asm("fma.rn.f32x2 %0, %1, %2, %3;" : "=l"(d) : "l"(a), "l"(b), "l"(c)); return d;
}
static __device__ __forceinline__ float ex2f(float v) {
    float r; asm("ex2.approx.f32 %0, %1;" : "=f"(r) : "f"(v)); return r;
}
static __device__ __forceinline__ float rcpf(float v) {
    float r; asm("rcp.approx.f32 %0, %1;" : "=f"(r) : "f"(v)); return r;
}

__global__ __launch_bounds__(TPB, 4)
void anfis_kernel(const float* __restrict__ x,
                  const float* __restrict__ c,
                  const float* __restrict__ log_sigma,
                  const float* __restrict__ cons,      // (R, M+1)
                  const int*   __restrict__ rules,     // (R, M)
                  float* __restrict__ out, int B)
{
    // Packed entry j (float2 over rule pair p = rules 2p,2p+1):
    //  j=0..7 : a_m = -h*log2(e) ; j=8..15: b_m = 2*h*c*log2(e)
    //  j=16   : k0 = -(sum h*c^2)*log2(e) ; j=17: bias ; j=18..25: w_m
    __shared__ float s_raw[R][26];
    __shared__ __align__(16) float s_pack[NPAIR * PW];

    const int tid = threadIdx.x;
    const float L2E = 1.4426950408889634f;

    if (tid < R) {
        const int r = tid;
        float k0 = 0.f;
        #pragma unroll
        for (int m = 0; m < M; m++) {
            int k = rules[r * M + m];
            float sg = expf(log_sigma[m * Kc + k]) + 1e-6f;
            float h  = 0.5f / (sg * sg);
            float cc = c[m * Kc + k];
            s_raw[r][m]      = -h * L2E;
            s_raw[r][8 + m]  = 2.f * h * cc * L2E;
            k0 -= h * cc * cc;
            s_raw[r][18 + m] = cons[r * (M + 1) + 1 + m];
        }
        s_raw[r][16] = k0 * L2E;
        s_raw[r][17] = cons[r * (M + 1)];
    }
    __syncthreads();
    if (tid < NPAIR * 28) {
        const int p = tid / 28, j = tid % 28;
        float v0 = (j < 26) ? s_raw[2 * p][j]     : 0.f;
        float v1 = (j < 26) ? s_raw[2 * p + 1][j] : 0.f;
        s_pack[p * PW + 2 * j]     = v0;
        s_pack[p * PW + 2 * j + 1] = v1;
    }
    __syncthreads();

    const int b0 = blockIdx.x * ROWS_PER_BLOCK + tid;
    if (b0 >= B) return;
    // B = 1048576 is divisible by ROWS_PER_BLOCK=512, so all RPT rows are valid.

    // ---- load RPT x rows (32B each, coalesced; kept as scalar f32) ----
    float xv[RPT][M];
    #pragma unroll
    for (int i = 0; i < RPT; i++) {
        const int b = b0 + i * TPB;
        const float4 xa = *(const float4*)(x + (size_t)b * M);
        const float4 xb = *(const float4*)(x + (size_t)b * M + 4);
        xv[i][0]=xa.x; xv[i][1]=xa.y; xv[i][2]=xa.z; xv[i][3]=xa.w;
        xv[i][4]=xb.x; xv[i][5]=xb.y; xv[i][6]=xb.z; xv[i][7]=xb.w;
    }

    float f[RPT][R], yr[RPT][R];
    float fs[RPT];
    #pragma unroll
    for (int i = 0; i < RPT; i++) fs[i] = 0.f;

    #pragma unroll
    for (int p = 0; p < NPAIR; p++) {
        const u64* S = (const u64*)(s_pack + p * PW);  // 26 packed entries, loaded once per 4 rows

        u64 e[RPT], t[RPT];
        #pragma unroll
        for (int i = 0; i < RPT; i++) { e[i] = S[16]; t[i] = S[17]; }

        #pragma unroll
        for (int m = 0; m < M; m++) {
            const u64 A = S[m], Bc = S[8 + m], W = S[18 + m];
            #pragma unroll
            for (int i = 0; i < RPT; i++) {
                const u64 px = pk2(xv[i][m], xv[i][m]);   // rematerializable mov
                e[i] = fma2(fma2(A, px, Bc), px, e[i]);
                t[i] = fma2(W, px, t[i]);
            }
        }

        #pragma unroll
        for (int i = 0; i < RPT; i++) {
            float ea, eb;
            upk2(e[i], ea, eb);
            const float fa = ex2f(ea), fb = ex2f(eb);
            f[i][2*p] = fa; f[i][2*p+1] = fb;
            fs[i] += fa + fb;
            upk2(t[i], yr[i][2*p], yr[i][2*p+1]);
        }
    }

    // ---- store y_r (no normalization needed) ----
    #pragma unroll
    for (int i = 0; i < RPT; i++) {
        const int b = b0 + i * TPB;
        float4* yo = (float4*)(out + (size_t)B * 9 + (size_t)b * R);
        yo[0] = make_float4(yr[i][0], yr[i][1], yr[i][2], yr[i][3]);
        yo[1] = make_float4(yr[i][4], yr[i][5], yr[i][6], yr[i][7]);
    }

    // ---- normalize, reduce, store y and w_norm ----
    #pragma unroll
    for (int i = 0; i < RPT; i++) {
        const int b = b0 + i * TPB;
        const float inv = rcpf(fs[i] + 1e-8f);
        float wn[R];
        float y = 0.f;
        #pragma unroll
        for (int r = 0; r < R; r++) {
            wn[r] = f[i][r] * inv;
            y = fmaf(wn[r], yr[i][r], y);
        }
        out[b] = y;
        float4* wo = (float4*)(out + (size_t)B + (size_t)b * R);
        wo[0] = make_float4(wn[0], wn[1], wn[2], wn[3]);
        wo[1] = make_float4(wn[4], wn[5], wn[6], wn[7]);
    }
}

extern "C" void kernel_launch(void* const* d_in, const int* in_sizes, int n_in,
                              void* d_out, int out_size)
{
    const float* x         = (const float*)d_in[0];
    const float* c         = (const float*)d_in[1];
    const float* log_sigma = (const float*)d_in[2];
    const float* cons      = (const float*)d_in[3];
    const int*   rules     = (const int*)d_in[4];
    float* out = (float*)d_out;

    const int B = in_sizes[0] / M;   // 1048576
    const int blocks = (B + ROWS_PER_BLOCK - 1) / ROWS_PER_BLOCK;  // 2048
    anfis_kernel<<<blocks, TPB>>>(x, c, log_sigma, cons, rules, out, B);
}